// round 1
// baseline (speedup 1.0000x reference)
#include <cuda_runtime.h>
#include <math.h>

#define BNS 0.9999950000374996f  // 1/sqrt(1+1e-5)

// ---------------- scratch (device globals; no runtime allocation) ----------
__device__ float g_k   [32*96*256];        // k pre/spikes   (TB,96,N)
__device__ float g_v   [32*384*256];       // v pre/spikes   (TB,384,N)
__device__ float g_w   [32*4*256];         // router pre/spikes (TB,4,N)
__device__ float g_q   [4*32*96*256];      // q pre/spikes   (E,TB,96,N)
__device__ float g_attn[4*32*256*256];     // attn           (E,TB,N,N)
__device__ float g_res [4*32*256*384];     // res pre/spikes (E,TB,N,C)
__device__ float g_y   [32*256*384];       // router-combined (TB,N,C)
__device__ float g_p   [32*384*256];       // proj pre/spikes (TB,C,N)
__device__ float g_xr  [32*384*256];       // x after attn residual
__device__ float g_h   [32*2048*256];      // fc1 pre/spikes (TB,2048,N)
__device__ float g_m   [32*1024*256];      // gated mlp mid  (TB,1024,N)
__device__ float g_f2  [32*384*256];       // fc2 pre/spikes

// ---------------- generic tiled SGEMM -------------------------------------
// C[z] (M x N, row-major) = epi( sum_k A[m,k]*B[k,n] )
// A addressed with strides (sAm,sAk), offset g*aG + b*aB  (z = g*Bcnt + b)
// B addressed with strides (sBk,sBn), offset g*bG + b*bB
// epi: out = (acc + bias[m]) * (scale[m]*BNS) + shift[m]   (null ptrs -> skip)
// AKF: A k-index contiguous;  BKF: B k-index contiguous (pick coalesced load)
template<bool AKF, bool BKF>
__global__ void gemm_kernel(
    const float* __restrict__ A, long aG, long aB, int sAm, int sAk,
    const float* __restrict__ B, long bG, long bB, int sBk, int sBn,
    float* __restrict__ C,
    const float* __restrict__ bias, const float* __restrict__ scale,
    const float* __restrict__ shift, int pG,
    int M, int N, int K, int Bcnt)
{
    __shared__ float As[16][68];
    __shared__ float Bs[16][68];
    int z = blockIdx.z;
    int g = z / Bcnt, b = z % Bcnt;
    A += (long)g * aG + (long)b * aB;
    B += (long)g * bG + (long)b * bB;
    C += (long)z * M * N;
    int m0 = blockIdx.y * 64;
    int n0 = blockIdx.x * 64;
    int tid = threadIdx.x;
    int tx = tid & 15, ty = tid >> 4;
    float acc[4][4] = {};
    for (int k0 = 0; k0 < K; k0 += 16) {
        #pragma unroll
        for (int l = 0; l < 4; l++) {
            int idx = tid + l * 256;
            // A tile -> As[kk][i]
            {
                int kk, i;
                if (AKF) { kk = idx & 15; i = idx >> 4; }
                else     { i = idx & 63; kk = idx >> 6; }
                int m = m0 + i;
                As[kk][i] = (m < M) ? A[(long)m * sAm + (long)(k0 + kk) * sAk] : 0.f;
            }
            // B tile -> Bs[kk][j]
            {
                int kk, j;
                if (BKF) { kk = idx & 15; j = idx >> 4; }
                else     { j = idx & 63; kk = idx >> 6; }
                int n = n0 + j;
                Bs[kk][j] = (n < N) ? B[(long)(k0 + kk) * sBk + (long)n * sBn] : 0.f;
            }
        }
        __syncthreads();
        #pragma unroll
        for (int kk = 0; kk < 16; kk++) {
            float4 a4 = *(const float4*)&As[kk][ty * 4];
            float4 b4 = *(const float4*)&Bs[kk][tx * 4];
            float av[4] = {a4.x, a4.y, a4.z, a4.w};
            float bv[4] = {b4.x, b4.y, b4.z, b4.w};
            #pragma unroll
            for (int u = 0; u < 4; u++)
                #pragma unroll
                for (int v = 0; v < 4; v++)
                    acc[u][v] = fmaf(av[u], bv[v], acc[u][v]);
        }
        __syncthreads();
    }
    #pragma unroll
    for (int u = 0; u < 4; u++) {
        int m = m0 + ty * 4 + u;
        if (m >= M) continue;
        float bi = bias  ? bias [g * pG + m]       : 0.f;
        float sc = scale ? scale[g * pG + m] * BNS : 1.f;
        float sh = shift ? shift[g * pG + m]       : 0.f;
        #pragma unroll
        for (int v = 0; v < 4; v++) {
            int n = n0 + tx * 4 + v;
            C[(long)m * N + n] = (acc[u][v] + bi) * sc + sh;
        }
    }
}

// ---------------- LIF (in place): buf = (slabs, TB=32, M), tb = t*8+b ------
__global__ void lif_kernel(float* __restrict__ buf, int slabs, long slabStride, int M)
{
    long tid = (long)blockIdx.x * blockDim.x + threadIdx.x;
    long total = (long)slabs * 8 * M;
    if (tid >= total) return;
    int  j = (int)(tid % M);
    long r = tid / M;
    int  b = (int)(r & 7);
    int  s = (int)(r >> 3);
    float* p = buf + (long)s * slabStride;
    float mem = 0.f;
    #pragma unroll
    for (int t = 0; t < 4; t++) {
        long idx = (long)(t * 8 + b) * M + j;
        float x = p[idx];
        mem = mem + (x - mem) * 0.5f;
        float sp = (mem >= 1.0f) ? 1.f : 0.f;
        p[idx] = sp;
        mem *= (1.f - sp);
    }
}

// ---------------- router-weighted expert sum: y[b,n,d] ---------------------
__global__ void combine_kernel()
{
    long tid = (long)blockIdx.x * blockDim.x + threadIdx.x;
    if (tid >= (long)32 * 256 * 384) return;
    int d = (int)(tid % 384);
    int n = (int)((tid / 384) % 256);
    int b = (int)(tid / (384 * 256));
    float acc = 0.f;
    #pragma unroll
    for (int e = 0; e < 4; e++)
        acc = fmaf(g_w[(b * 4 + e) * 256 + n],
                   g_res[(((long)(e * 32 + b) * 256) + n) * 384 + d], acc);
    g_y[tid] = acc;
}

// ---------------- elementwise add -----------------------------------------
__global__ void add_kernel(const float* __restrict__ a, const float* __restrict__ b,
                           float* __restrict__ o, int n)
{
    int i = blockIdx.x * 256 + threadIdx.x;
    if (i < n) o[i] = a[i] + b[i];
}

// ---------------- fused dwconv3x3 + bias + BN + LIF + gate -----------------
// x1 = g_h[:, 0:1024, :] (spikes), x2 = g_h[:, 1024:2048, :] (spikes)
// g_m[tb,c,n] = LIF(BN(conv(x1)+b)) * x2
__global__ void dwconv_gate_kernel(const float* __restrict__ dw_w, const float* __restrict__ dw_b,
                                   const float* __restrict__ dw_g, const float* __restrict__ dw_be)
{
    int tid = blockIdx.x * 256 + threadIdx.x;
    if (tid >= 8 * 1024 * 256) return;
    int n  = tid & 255;
    int c  = (tid >> 8) & 1023;
    int b  = tid >> 18;
    int hh = n >> 4, ww = n & 15;
    float wk[9];
    #pragma unroll
    for (int i = 0; i < 9; i++) wk[i] = dw_w[c * 9 + i];
    float bi = dw_b[c], sc = dw_g[c] * BNS, sh = dw_be[c];
    float mem = 0.f;
    #pragma unroll
    for (int t = 0; t < 4; t++) {
        int tb = t * 8 + b;
        const float* x1 = g_h + ((long)tb * 2048 + c) * 256;
        float acc = bi;
        #pragma unroll
        for (int di = 0; di < 3; di++) {
            int yy = hh + di - 1;
            if (yy < 0 || yy > 15) continue;
            #pragma unroll
            for (int dj = 0; dj < 3; dj++) {
                int xx = ww + dj - 1;
                if (xx < 0 || xx > 15) continue;
                acc = fmaf(wk[di * 3 + dj], x1[yy * 16 + xx], acc);
            }
        }
        float pre = acc * sc + sh;
        mem = mem + (pre - mem) * 0.5f;
        float sp = (mem >= 1.f) ? 1.f : 0.f;
        mem *= (1.f - sp);
        float x2 = g_h[((long)tb * 2048 + 1024 + c) * 256 + n];
        g_m[((long)tb * 1024 + c) * 256 + n] = sp * x2;
    }
}

// ---------------------------------------------------------------------------
extern "C" void kernel_launch(void* const* d_in, const int* in_sizes, int n_in,
                              void* d_out, int out_size)
{
    const float* x         = (const float*)d_in[0];
    const float* k_w       = (const float*)d_in[2];
    const float* v_w       = (const float*)d_in[3];
    const float* router_w  = (const float*)d_in[4];
    const float* router_b  = (const float*)d_in[5];
    const float* router_g  = (const float*)d_in[6];
    const float* router_be = (const float*)d_in[7];
    const float* exp_w     = (const float*)d_in[8];
    const float* exp_g     = (const float*)d_in[9];
    const float* exp_b     = (const float*)d_in[10];
    const float* proj_w    = (const float*)d_in[11];
    const float* proj_b    = (const float*)d_in[12];
    const float* proj_g    = (const float*)d_in[13];
    const float* proj_be   = (const float*)d_in[14];
    const float* fc1_w     = (const float*)d_in[15];
    const float* fc1_b     = (const float*)d_in[16];
    const float* fc1_g     = (const float*)d_in[17];
    const float* fc1_be    = (const float*)d_in[18];
    const float* dw_w      = (const float*)d_in[19];
    const float* dw_b      = (const float*)d_in[20];
    const float* dw_g      = (const float*)d_in[21];
    const float* dw_be     = (const float*)d_in[22];
    const float* fc2_w     = (const float*)d_in[23];
    const float* fc2_b     = (const float*)d_in[24];
    const float* fc2_g     = (const float*)d_in[25];
    const float* fc2_be    = (const float*)d_in[26];
    float* out = (float*)d_out;

    float *pk, *pv, *pw, *pq, *pattn, *pres, *py, *pp, *pxr, *ph, *pm, *pf2;
    cudaGetSymbolAddress((void**)&pk,   g_k);
    cudaGetSymbolAddress((void**)&pv,   g_v);
    cudaGetSymbolAddress((void**)&pw,   g_w);
    cudaGetSymbolAddress((void**)&pq,   g_q);
    cudaGetSymbolAddress((void**)&pattn,g_attn);
    cudaGetSymbolAddress((void**)&pres, g_res);
    cudaGetSymbolAddress((void**)&py,   g_y);
    cudaGetSymbolAddress((void**)&pp,   g_p);
    cudaGetSymbolAddress((void**)&pxr,  g_xr);
    cudaGetSymbolAddress((void**)&ph,   g_h);
    cudaGetSymbolAddress((void**)&pm,   g_m);
    cudaGetSymbolAddress((void**)&pf2,  g_f2);

    const long XB = 384 * 256;   // per-tb x slab
    dim3 blk(256);

    // --- SSA pre-activations ---
    // k = k_w @ xs                          (TB,96,N)
    gemm_kernel<true,false><<<dim3(4,2,32),blk>>>(k_w,0,0,384,1, x,0,XB,256,1,
        pk, nullptr,nullptr,nullptr,0, 96,256,384,32);
    // v = v_w @ xs                          (TB,384,N)
    gemm_kernel<true,false><<<dim3(4,6,32),blk>>>(v_w,0,0,384,1, x,0,XB,256,1,
        pv, nullptr,nullptr,nullptr,0, 384,256,384,32);
    // w = bn(router_w @ xs + router_b)      (TB,4,N)
    gemm_kernel<true,false><<<dim3(4,1,32),blk>>>(router_w,0,0,384,1, x,0,XB,256,1,
        pw, router_b,router_g,router_be,0, 4,256,384,32);
    // q = bn_e(exp_w[e] @ xs)               (E,TB,96,N)
    gemm_kernel<true,false><<<dim3(4,2,128),blk>>>(exp_w,(long)96*384,0,384,1, x,0,XB,256,1,
        pq, nullptr,exp_g,exp_b,96, 96,256,384,32);

    // --- LIF -> spikes ---
    lif_kernel<<<(8*96*256+255)/256,blk>>>(pk, 1, 0, 96*256);
    lif_kernel<<<(8*384*256+255)/256,blk>>>(pv, 1, 0, 384*256);
    lif_kernel<<<(8*4*256+255)/256,blk>>>(pw, 1, 0, 4*256);
    lif_kernel<<<(4*8*96*256+255)/256,blk>>>(pq, 4, (long)32*96*256, 96*256);

    // attn[e,b] = q[e,b]^T @ k[b]           (E,TB,N,N), exact integer
    gemm_kernel<false,false><<<dim3(4,4,128),blk>>>(pq,(long)32*96*256,(long)96*256,1,256,
        pk,0,(long)96*256,256,1, pattn, nullptr,nullptr,nullptr,0, 256,256,96,32);
    // res[e,b] = attn[e,b] @ v[b]^T         (E,TB,N,C), exact integer
    gemm_kernel<true,true><<<dim3(6,4,128),blk>>>(pattn,(long)32*65536,65536,256,1,
        pv,0,XB,1,256, pres, nullptr,nullptr,nullptr,0, 256,384,256,32);
    lif_kernel<<<(4*8*256*384+255)/256,blk>>>(pres, 4, (long)32*256*384, 256*384);

    // y[b,n,d] = sum_e w[b,e,n]*res[e,b,n,d]
    combine_kernel<<<(32*256*384+255)/256,blk>>>();

    // proj: bn(proj_w @ y + proj_b) -> lif  (TB,C,N)
    gemm_kernel<true,true><<<dim3(4,6,32),blk>>>(proj_w,0,0,384,1,
        py,0,(long)256*384,1,384, pp, proj_b,proj_g,proj_be,0, 384,256,384,32);
    lif_kernel<<<(8*384*256+255)/256,blk>>>(pp, 1, 0, 384*256);
    // x = x + attn_out
    add_kernel<<<(32*384*256+255)/256,blk>>>(x, pp, pxr, 32*384*256);

    // --- MLP ---
    // h = lif(bn(fc1_w @ x + fc1_b))        (TB,2048,N)
    gemm_kernel<true,false><<<dim3(4,32,32),blk>>>(fc1_w,0,0,384,1, pxr,0,XB,256,1,
        ph, fc1_b,fc1_g,fc1_be,0, 2048,256,384,32);
    lif_kernel<<<(8*2048*256+255)/256,blk>>>(ph, 1, 0, 2048*256);
    // m = lif(bn(dwconv(x1)+b)) * x2        (TB,1024,N)
    dwconv_gate_kernel<<<(8*1024*256+255)/256,blk>>>(dw_w, dw_b, dw_g, dw_be);
    // f2 = lif(bn(fc2_w @ m + fc2_b))       (TB,C,N)
    gemm_kernel<true,false><<<dim3(4,6,32),blk>>>(fc2_w,0,0,1024,1, pm,0,(long)1024*256,256,1,
        pf2, fc2_b,fc2_g,fc2_be,0, 384,256,1024,32);
    lif_kernel<<<(8*384*256+255)/256,blk>>>(pf2, 1, 0, 384*256);

    // out = x + m
    add_kernel<<<(32*384*256+255)/256,blk>>>(pxr, pf2, out, 32*384*256);
}